// round 7
// baseline (speedup 1.0000x reference)
#include <cuda_runtime.h>
#include <cuda_fp16.h>
#include <math.h>

#define N_NODES 500000
#define N_EDGES 3000000

#define SCAN_ITEMS 8
#define SCAN_BS 256
#define SCAN_CHUNK (SCAN_ITEMS * SCAN_BS)           // 2048
#define SCAN_NBLK ((N_NODES + SCAN_CHUNK - 1) / SCAN_CHUNK)  // 245

// ---- device scratch (no allocations allowed) ----
__device__ int    g_deg[N_NODES];
__device__ int    g_off[N_NODES];      // CSR exclusive offsets
__device__ int    g_cur[N_NODES];      // scatter cursors
__device__ int    g_csr[N_EDGES];      // src node per incoming edge, grouped by dst
__device__ int    g_order[N_NODES];    // nodes sorted by degree (divergence control)
__device__ int    g_bsum[SCAN_NBLK];
__device__ int    g_bpre[SCAN_NBLK];
__device__ int    g_dhist[64];
__device__ int    g_dcur[64];
__device__ float  g_p[N_NODES * 16];   // p_i = x_i@(A1-A2)+b1a (fp32)
__device__ __half g_v[N_NODES * 16];   // v_j = x_j@A2 (fp16, 32B/row)
__device__ float4 g_q[N_NODES];        // q_i = b2a + h_i@(W2top-W2bot)
__device__ uint2  g_r[N_NODES];        // r_j = h_j@W2bot (fp16x4, 8B)

// ---------------------------------------------------------------------------
__global__ void zero_kernel() {
    int i = blockIdx.x * blockDim.x + threadIdx.x;
    int stride = gridDim.x * blockDim.x;
    for (int j = i; j < N_NODES; j += stride) g_deg[j] = 0;
    if (i < 64) g_dhist[i] = 0;
}

__global__ void __launch_bounds__(256) hist_kernel(const int* __restrict__ ei) {
    int e = blockIdx.x * 256 + threadIdx.x;
    if (e >= N_EDGES) return;
    atomicAdd(&g_deg[ei[N_EDGES + e]], 1);
}

// ---- exclusive scan of g_deg -> g_off (and g_cur) : 3 kernels ----
__global__ void __launch_bounds__(SCAN_BS) scan1_kernel() {
    __shared__ int sh[SCAN_BS];
    int b = blockIdx.x, t = threadIdx.x;
    int base = b * SCAN_CHUNK + t * SCAN_ITEMS;
    int sum = 0;
#pragma unroll
    for (int k = 0; k < SCAN_ITEMS; k++) {
        int i = base + k;
        if (i < N_NODES) sum += g_deg[i];
    }
    sh[t] = sum; __syncthreads();
    for (int off = 128; off > 0; off >>= 1) {
        if (t < off) sh[t] += sh[t + off];
        __syncthreads();
    }
    if (t == 0) g_bsum[b] = sh[0];
}

__global__ void __launch_bounds__(SCAN_BS) scan2_kernel() {
    __shared__ int sh[SCAN_BS];
    int t = threadIdx.x;
    int v = (t < SCAN_NBLK) ? g_bsum[t] : 0;
    sh[t] = v; __syncthreads();
    for (int off = 1; off < SCAN_BS; off <<= 1) {
        int tmp = (t >= off) ? sh[t - off] : 0;
        __syncthreads();
        sh[t] += tmp;
        __syncthreads();
    }
    if (t < SCAN_NBLK) g_bpre[t] = sh[t] - v;  // exclusive
}

__global__ void __launch_bounds__(SCAN_BS) scan3_kernel() {
    __shared__ int sh[SCAN_BS];
    int b = blockIdx.x, t = threadIdx.x;
    int base = b * SCAN_CHUNK + t * SCAN_ITEMS;
    int vals[SCAN_ITEMS];
    int tsum = 0;
#pragma unroll
    for (int k = 0; k < SCAN_ITEMS; k++) {
        int i = base + k;
        vals[k] = (i < N_NODES) ? g_deg[i] : 0;
        tsum += vals[k];
    }
    sh[t] = tsum; __syncthreads();
    for (int off = 1; off < SCAN_BS; off <<= 1) {
        int tmp = (t >= off) ? sh[t - off] : 0;
        __syncthreads();
        sh[t] += tmp;
        __syncthreads();
    }
    int running = g_bpre[b] + sh[t] - tsum;
#pragma unroll
    for (int k = 0; k < SCAN_ITEMS; k++) {
        int i = base + k;
        if (i < N_NODES) { g_off[i] = running; g_cur[i] = running; }
        running += vals[k];
    }
}

// ---- degree counting sort -> g_order ----
__global__ void __launch_bounds__(256) dhist_kernel() {
    int i = blockIdx.x * 256 + threadIdx.x;
    if (i >= N_NODES) return;
    int d = g_deg[i]; if (d > 63) d = 63;
    atomicAdd(&g_dhist[d], 1);
}

__global__ void scan64_kernel() {
    __shared__ int sh[64];
    int t = threadIdx.x;
    int v = g_dhist[t];
    sh[t] = v; __syncthreads();
    for (int off = 1; off < 64; off <<= 1) {
        int tmp = (t >= off) ? sh[t - off] : 0;
        __syncthreads();
        sh[t] += tmp;
        __syncthreads();
    }
    g_dcur[t] = sh[t] - v;  // exclusive
}

__global__ void __launch_bounds__(256) dscatter_kernel() {
    int i = blockIdx.x * 256 + threadIdx.x;
    if (i >= N_NODES) return;
    int d = g_deg[i]; if (d > 63) d = 63;
    int pos = atomicAdd(&g_dcur[d], 1);
    g_order[pos] = i;
}

// ---- edge scatter into CSR ----
__global__ void __launch_bounds__(256) escatter_kernel(const int* __restrict__ ei) {
    int e = blockIdx.x * 256 + threadIdx.x;
    if (e >= N_EDGES) return;
    int s = ei[e];
    int d = ei[N_EDGES + e];
    int slot = atomicAdd(&g_cur[d], 1);
    g_csr[slot] = s;
}

// ---- per-node precompute: p_i (fp32), v_i (fp16) ----
__global__ void __launch_bounds__(256) precompute_kernel(
    const float* __restrict__ x,
    const float* __restrict__ w1a, const float* __restrict__ b1a) {
    __shared__ float sw[96], sb[16];
    int t = threadIdx.x;
    if (t < 96) sw[t] = w1a[t];
    if (t < 16) sb[t] = b1a[t];
    __syncthreads();
    int i = blockIdx.x * 256 + t;
    if (i >= N_NODES) return;
    float x0 = x[3 * i], x1 = x[3 * i + 1], x2 = x[3 * i + 2];
    float p[16]; __half vh[16];
#pragma unroll
    for (int k = 0; k < 16; k++) {
        float v = x0 * sw[48 + k] + x1 * sw[64 + k] + x2 * sw[80 + k];   // x@A2
        float pp = sb[k] + x0 * (sw[k] - sw[48 + k]) + x1 * (sw[16 + k] - sw[64 + k])
                 + x2 * (sw[32 + k] - sw[80 + k]);                        // x@(A1-A2)+b
        p[k] = pp; vh[k] = __float2half_rn(v);
    }
    float4* pp4 = (float4*)(g_p + (long long)i * 16);
    const float4* ps = (const float4*)p;
#pragma unroll
    for (int q = 0; q < 4; q++) pp4[q] = ps[q];
    uint4* vv4 = (uint4*)g_v;
    const uint4* vs = (const uint4*)vh;
    vv4[2 * i] = vs[0]; vv4[2 * i + 1] = vs[1];
}

__device__ __forceinline__ void unpack8(uint4 u, float* f) {
    const __half2* h = (const __half2*)&u;
#pragma unroll
    for (int q = 0; q < 4; q++) {
        float2 p = __half22float2(h[q]);
        f[2 * q] = p.x; f[2 * q + 1] = p.y;
    }
}

// ---------------------------------------------------------------------------
// edge1_pull: per node, max over in-edges of relu(p_i+v_j)@W1b+b1b (init 0 ==
// where+relu fusion). Epilogue computes q_i, r_i from registered h -> h never
// stored. No atomics anywhere.
// ---------------------------------------------------------------------------
__global__ void __launch_bounds__(256) edge1_pull_kernel(
    const float* __restrict__ w1b, const float* __restrict__ b1b,
    const float* __restrict__ w2a, const float* __restrict__ b2a) {
    __shared__ float sw1b[256], sb1b[16], sw2a[128], sb2a[4];
    int t = threadIdx.x;
    sw1b[t] = w1b[t];
    if (t < 16)  sb1b[t] = b1b[t];
    if (t < 128) sw2a[t] = w2a[t];
    if (t < 4)   sb2a[t] = b2a[t];
    __syncthreads();

    int gt = blockIdx.x * 256 + t;
    if (gt >= N_NODES) return;
    int node = g_order[gt];
    int start = g_off[node];
    int deg   = g_deg[node];

    float p[16];
    {
        const float4* pp = (const float4*)(g_p + (long long)node * 16);
#pragma unroll
        for (int q = 0; q < 4; q++) {
            float4 c = pp[q];
            p[4 * q] = c.x; p[4 * q + 1] = c.y; p[4 * q + 2] = c.z; p[4 * q + 3] = c.w;
        }
    }

    float acc[16];
#pragma unroll
    for (int k = 0; k < 16; k++) acc[k] = 0.f;

    const uint4* vt = (const uint4*)g_v;
    for (int j = 0; j < deg; j++) {
        int s = g_csr[start + j];
        uint4 va = __ldg(&vt[2 * s]);
        uint4 vb = __ldg(&vt[2 * s + 1]);
        float v[16];
        unpack8(va, v); unpack8(vb, v + 8);
        float z[16];
#pragma unroll
        for (int k = 0; k < 16; k++) z[k] = fmaxf(p[k] + v[k], 0.f);
#pragma unroll
        for (int k = 0; k < 16; k++) {
            float a = sb1b[k];
#pragma unroll
            for (int c = 0; c < 16; c++) a = fmaf(z[c], sw1b[c * 16 + k], a);
            acc[k] = fmaxf(acc[k], a);
        }
    }

    // q = b2a + h@(W2top - W2bot) ; r = h@W2bot   (h == acc, already >= 0)
    float q[4], r[4];
#pragma unroll
    for (int n = 0; n < 4; n++) {
        float aq = sb2a[n], ar = 0.f;
#pragma unroll
        for (int c = 0; c < 16; c++) {
            float hb = sw2a[(16 + c) * 4 + n];
            aq = fmaf(acc[c], sw2a[c * 4 + n] - hb, aq);
            ar = fmaf(acc[c], hb, ar);
        }
        q[n] = aq; r[n] = ar;
    }
    g_q[node] = make_float4(q[0], q[1], q[2], q[3]);
    __half2 r01 = __floats2half2_rn(r[0], r[1]);
    __half2 r23 = __floats2half2_rn(r[2], r[3]);
    uint2 ru;
    ru.x = *reinterpret_cast<unsigned*>(&r01);
    ru.y = *reinterpret_cast<unsigned*>(&r23);
    g_r[node] = ru;
}

// ---------------------------------------------------------------------------
// edge2_pull: per node, max over edges of relu(q_i+r_j)@W2b+b2b, then fused
// -inf->0 fixup + log_softmax, write final output row.
// ---------------------------------------------------------------------------
__global__ void __launch_bounds__(256) edge2_pull_kernel(
    const float* __restrict__ w2b, const float* __restrict__ b2b,
    float4* __restrict__ out4) {
    __shared__ float sw[16], sb[4];
    int t = threadIdx.x;
    if (t < 16) sw[t] = w2b[t];
    if (t < 4)  sb[t] = b2b[t];
    __syncthreads();

    int gt = blockIdx.x * 256 + t;
    if (gt >= N_NODES) return;
    int node = g_order[gt];
    int start = g_off[node];
    int deg   = g_deg[node];

    float4 qv = g_q[node];
    float q[4] = {qv.x, qv.y, qv.z, qv.w};

    const float NI = __int_as_float(0xFF800000);
    float acc[4] = {NI, NI, NI, NI};
    for (int j = 0; j < deg; j++) {
        int s = g_csr[start + j];
        uint2 ru = __ldg(&g_r[s]);
        __half2 r01 = *reinterpret_cast<__half2*>(&ru.x);
        __half2 r23 = *reinterpret_cast<__half2*>(&ru.y);
        float2 f01 = __half22float2(r01);
        float2 f23 = __half22float2(r23);
        float z[4] = {fmaxf(q[0] + f01.x, 0.f), fmaxf(q[1] + f01.y, 0.f),
                      fmaxf(q[2] + f23.x, 0.f), fmaxf(q[3] + f23.y, 0.f)};
#pragma unroll
        for (int n = 0; n < 4; n++) {
            float a = sb[n];
#pragma unroll
            for (int c = 0; c < 4; c++) a = fmaf(z[c], sw[c * 4 + n], a);
            acc[n] = fmaxf(acc[n], a);
        }
    }
    if (deg == 0) { acc[0] = acc[1] = acc[2] = acc[3] = 0.f; }

    float m = fmaxf(fmaxf(acc[0], acc[1]), fmaxf(acc[2], acc[3]));
    float s = expf(acc[0] - m) + expf(acc[1] - m) + expf(acc[2] - m) + expf(acc[3] - m);
    float l = m + logf(s);
    out4[node] = make_float4(acc[0] - l, acc[1] - l, acc[2] - l, acc[3] - l);
}

// ---------------------------------------------------------------------------
extern "C" void kernel_launch(void* const* d_in, const int* in_sizes, int n_in,
                              void* d_out, int out_size) {
    const float* x   = (const float*)d_in[0];
    const int*   ei  = (const int*)d_in[1];
    const float* w1a = (const float*)d_in[2];
    const float* b1a = (const float*)d_in[3];
    const float* w1b = (const float*)d_in[4];
    const float* b1b = (const float*)d_in[5];
    const float* w2a = (const float*)d_in[6];
    const float* b2a = (const float*)d_in[7];
    const float* w2b = (const float*)d_in[8];
    const float* b2b = (const float*)d_in[9];
    float4* out = (float4*)d_out;

    int nb = (N_NODES + 255) / 256;
    int eb = (N_EDGES + 255) / 256;

    zero_kernel<<<1024, 256>>>();
    hist_kernel<<<eb, 256>>>(ei);
    dhist_kernel<<<nb, 256>>>();
    scan1_kernel<<<SCAN_NBLK, SCAN_BS>>>();
    scan2_kernel<<<1, SCAN_BS>>>();
    scan3_kernel<<<SCAN_NBLK, SCAN_BS>>>();
    scan64_kernel<<<1, 64>>>();
    dscatter_kernel<<<nb, 256>>>();
    escatter_kernel<<<eb, 256>>>(ei);
    precompute_kernel<<<nb, 256>>>(x, w1a, b1a);
    edge1_pull_kernel<<<nb, 256>>>(w1b, b1b, w2a, b2a);
    edge2_pull_kernel<<<nb, 256>>>(w2b, b2b, out);
}

// round 10
// speedup vs baseline: 1.7835x; 1.7835x over previous
#include <cuda_runtime.h>
#include <math.h>

#define N_NODES 500000
#define N_EDGES 3000000

// Scratch buffers (device globals — no allocation allowed)
__device__ float  g_h1[N_NODES * 16];   // layer-1 fp32 accumulator (atomic target)
__device__ float4 g_x4[N_NODES];        // padded x for single-load gathers
__device__ float4 g_q[N_NODES];         // q_i = b2a + h_i@(Wtop-Wbot)
__device__ float4 g_r[N_NODES];         // r_j = h_j@Wbot

// ---------------------------------------------------------------------------
// Kernel 0: pack x -> float4 table, zero g_h1, set out <- -inf.
// ---------------------------------------------------------------------------
__global__ void init_kernel(const float* __restrict__ x, float4* __restrict__ out4) {
    int i = blockIdx.x * blockDim.x + threadIdx.x;
    int stride = gridDim.x * blockDim.x;
    for (int j = i; j < N_NODES; j += stride)
        g_x4[j] = make_float4(x[3 * j], x[3 * j + 1], x[3 * j + 2], 0.f);
    float4* a = (float4*)g_h1;
    const float4 z = make_float4(0.f, 0.f, 0.f, 0.f);
    for (int j = i; j < N_NODES * 4; j += stride) a[j] = z;
    const float NI = __int_as_float(0xFF800000);  // -inf
    const float4 ni = make_float4(NI, NI, NI, NI);
    for (int j = i; j < N_NODES; j += stride) out4[j] = ni;
}

// float atomic-max via signed/unsigned bit trick (exact, order-independent)
__device__ __forceinline__ void atomic_max_float(float* addr, float v) {
    if (v >= 0.f) atomicMax((int*)addr, __float_as_int(v));
    else          atomicMin((unsigned int*)addr, __float_as_uint(v));
}

// ---------------------------------------------------------------------------
// Kernel 1: EdgeConv layer 1.  g_x4 -> scatter-max into g_h1[N,16].
// 2 gather wf + 4 vector-probe wf per edge; probes are stale-safe
// (atomicMax remains the correctness guard).
// ---------------------------------------------------------------------------
__global__ void __launch_bounds__(256) edge1_kernel(
    const int* __restrict__ ei,
    const float* __restrict__ w1a, const float* __restrict__ b1a,
    const float* __restrict__ w1b, const float* __restrict__ b1b) {
    __shared__ float sw1a[96], sb1a[16], sw1b[256], sb1b[16];
    int t = threadIdx.x;
    if (t < 96)  sw1a[t] = w1a[t];
    if (t < 16)  { sb1a[t] = b1a[t]; sb1b[t] = b1b[t]; }
    sw1b[t] = w1b[t];                   // blockDim == 256
    __syncthreads();

    int e = blockIdx.x * 256 + t;
    if (e >= N_EDGES) return;
    int s = ei[e];
    int d = ei[N_EDGES + e];

    float4 xi = __ldg(&g_x4[d]);
    float4 xj = __ldg(&g_x4[s]);
    float in6[6] = {xi.x, xi.y, xi.z, xj.x - xi.x, xj.y - xi.y, xj.z - xi.z};

    float hid[16];
#pragma unroll
    for (int k = 0; k < 16; k++) {
        float a = sb1a[k];
#pragma unroll
        for (int c = 0; c < 6; c++) a = fmaf(in6[c], sw1a[c * 16 + k], a);
        hid[k] = fmaxf(a, 0.f);
    }

    float outv[16];
#pragma unroll
    for (int k = 0; k < 16; k++) {
        float a = sb1b[k];
#pragma unroll
        for (int j = 0; j < 16; j++) a = fmaf(hid[j], sw1b[j * 16 + k], a);
        outv[k] = a;
    }

    // Vector probe of the current accumulator row (4 loads, not 16)
    float* dstp = g_h1 + (long long)d * 16;
    float cur[16];
#pragma unroll
    for (int q = 0; q < 4; q++) {
        float4 c = ((const float4*)dstp)[q];
        cur[4 * q] = c.x; cur[4 * q + 1] = c.y; cur[4 * q + 2] = c.z; cur[4 * q + 3] = c.w;
    }
#pragma unroll
    for (int k = 0; k < 16; k++) {
        // init 0 => non-positive can't win; stale cur => extra RED, still correct
        if (outv[k] > 0.f && outv[k] > cur[k])
            atomicMax((int*)(dstp + k), __float_as_int(outv[k]));
    }
}

// ---------------------------------------------------------------------------
// Kernel 1.5: per-node factoring of layer 2's first GEMM (coalesced).
// q_i = b2a + h_i@(Wtop - Wbot),  r_i = h_i@Wbot.
// Per-edge then: z4 = relu(q[dst] + r[src]).
// ---------------------------------------------------------------------------
__global__ void __launch_bounds__(256) qr_kernel(
    const float* __restrict__ w2a, const float* __restrict__ b2a) {
    __shared__ float sw[128], sb[4];
    int t = threadIdx.x;
    if (t < 128) sw[t] = w2a[t];
    if (t < 4)   sb[t] = b2a[t];
    __syncthreads();
    int i = blockIdx.x * 256 + t;
    if (i >= N_NODES) return;

    float h[16];
    const float4* hp = (const float4*)(g_h1 + (long long)i * 16);
#pragma unroll
    for (int q = 0; q < 4; q++) {
        float4 c = hp[q];
        h[4 * q] = c.x; h[4 * q + 1] = c.y; h[4 * q + 2] = c.z; h[4 * q + 3] = c.w;
    }

    float q[4], r[4];
#pragma unroll
    for (int n = 0; n < 4; n++) {
        float aq = sb[n], ar = 0.f;
#pragma unroll
        for (int c = 0; c < 16; c++) {
            float wb = sw[(16 + c) * 4 + n];           // Wbot[c][n]
            aq = fmaf(h[c], sw[c * 4 + n] - wb, aq);   // h@(Wtop-Wbot)
            ar = fmaf(h[c], wb, ar);                   // h@Wbot
        }
        q[n] = aq; r[n] = ar;
    }
    g_q[i] = make_float4(q[0], q[1], q[2], q[3]);
    g_r[i] = make_float4(r[0], r[1], r[2], r[3]);
}

// ---------------------------------------------------------------------------
// Kernel 2: EdgeConv layer 2, factored.  Only 3 wavefronts/edge:
// q[d] gather + r[s] gather + out probe. z4=relu(q+r); out=z4@W2b+b2b; max.
// (s==d self-loops are handled naturally: q_i + r_i == b2a + h_i@Wtop.)
// ---------------------------------------------------------------------------
__global__ void __launch_bounds__(256) edge2_kernel(
    const int* __restrict__ ei,
    const float* __restrict__ w2b, const float* __restrict__ b2b,
    float* __restrict__ out) {
    __shared__ float sw[16], sb[4];
    int t = threadIdx.x;
    if (t < 16) sw[t] = w2b[t];
    if (t < 4)  sb[t] = b2b[t];
    __syncthreads();

    int e = blockIdx.x * 256 + t;
    if (e >= N_EDGES) return;
    int s = ei[e];
    int d = ei[N_EDGES + e];

    float4 qv = __ldg(&g_q[d]);
    float4 rv = __ldg(&g_r[s]);
    float z[4] = {fmaxf(qv.x + rv.x, 0.f), fmaxf(qv.y + rv.y, 0.f),
                  fmaxf(qv.z + rv.z, 0.f), fmaxf(qv.w + rv.w, 0.f)};

    float ov[4];
#pragma unroll
    for (int k = 0; k < 4; k++) {
        float a = sb[k];
#pragma unroll
        for (int j = 0; j < 4; j++) a = fmaf(z[j], sw[j * 4 + k], a);
        ov[k] = a;
    }

    float* dstp = out + (long long)d * 4;
    float4 c = *((const float4*)dstp);   // single vector probe; stale-safe
    float cur[4] = {c.x, c.y, c.z, c.w};
#pragma unroll
    for (int k = 0; k < 4; k++) {
        if (!(ov[k] <= cur[k]))
            atomic_max_float(dstp + k, ov[k]);
    }
}

// ---------------------------------------------------------------------------
// Kernel 3: finalize.  -inf -> 0, then log_softmax over the 4 channels.
// ---------------------------------------------------------------------------
__global__ void __launch_bounds__(256) finalize_kernel(float4* __restrict__ out4) {
    int i = blockIdx.x * 256 + threadIdx.x;
    if (i >= N_NODES) return;
    float4 v = out4[i];
    if (!isfinite(v.x)) v.x = 0.f;
    if (!isfinite(v.y)) v.y = 0.f;
    if (!isfinite(v.z)) v.z = 0.f;
    if (!isfinite(v.w)) v.w = 0.f;
    float m = fmaxf(fmaxf(v.x, v.y), fmaxf(v.z, v.w));
    float s = expf(v.x - m) + expf(v.y - m) + expf(v.z - m) + expf(v.w - m);
    float l = m + logf(s);
    v.x -= l; v.y -= l; v.z -= l; v.w -= l;
    out4[i] = v;
}

extern "C" void kernel_launch(void* const* d_in, const int* in_sizes, int n_in,
                              void* d_out, int out_size) {
    const float* x   = (const float*)d_in[0];
    const int*   ei  = (const int*)d_in[1];
    const float* w1a = (const float*)d_in[2];
    const float* b1a = (const float*)d_in[3];
    const float* w1b = (const float*)d_in[4];
    const float* b1b = (const float*)d_in[5];
    const float* w2a = (const float*)d_in[6];
    const float* b2a = (const float*)d_in[7];
    const float* w2b = (const float*)d_in[8];
    const float* b2b = (const float*)d_in[9];
    float* out = (float*)d_out;

    init_kernel<<<2048, 256>>>(x, (float4*)out);
    int eb = (N_EDGES + 255) / 256;
    int nb = (N_NODES + 255) / 256;
    edge1_kernel<<<eb, 256>>>(ei, w1a, b1a, w1b, b1b);
    qr_kernel<<<nb, 256>>>(w2a, b2a);
    edge2_kernel<<<eb, 256>>>(ei, w2b, b2b, out);
    finalize_kernel<<<nb, 256>>>((float4*)out);
}

// round 11
// speedup vs baseline: 1.8610x; 1.0435x over previous
#include <cuda_runtime.h>
#include <math.h>

#define N_NODES 500000
#define N_EDGES 3000000

// Scratch buffers (device globals — no allocation allowed)
__device__ float  g_h1[N_NODES * 16];   // layer-1 fp32 accumulator (atomic target)
__device__ float4 g_x4[N_NODES];        // padded x for single-load gathers
__device__ float4 g_q[N_NODES];         // q_i = b2a + h_i@(Wtop-Wbot)
__device__ float4 g_r[N_NODES];         // r_j = h_j@Wbot

// ---------------------------------------------------------------------------
// Kernel 0: pack x -> float4 table, zero g_h1, set out <- -inf.
// ---------------------------------------------------------------------------
__global__ void init_kernel(const float* __restrict__ x, float4* __restrict__ out4) {
    int i = blockIdx.x * blockDim.x + threadIdx.x;
    int stride = gridDim.x * blockDim.x;
    for (int j = i; j < N_NODES; j += stride)
        g_x4[j] = make_float4(x[3 * j], x[3 * j + 1], x[3 * j + 2], 0.f);
    float4* a = (float4*)g_h1;
    const float4 z = make_float4(0.f, 0.f, 0.f, 0.f);
    for (int j = i; j < N_NODES * 4; j += stride) a[j] = z;
    const float NI = __int_as_float(0xFF800000);  // -inf
    const float4 ni = make_float4(NI, NI, NI, NI);
    for (int j = i; j < N_NODES; j += stride) out4[j] = ni;
}

// float atomic-max via signed/unsigned bit trick (exact, order-independent)
__device__ __forceinline__ void atomic_max_float(float* addr, float v) {
    if (v >= 0.f) atomicMax((int*)addr, __float_as_int(v));
    else          atomicMin((unsigned int*)addr, __float_as_uint(v));
}

// 256-bit load of 8 consecutive floats (Blackwell LDG.E.256).
// Address must be 32B-aligned; g_h1 rows are 64B-aligned.
__device__ __forceinline__ void ld256(const float* p, float* v) {
#if defined(__CUDA_ARCH__) && (__CUDA_ARCH__ >= 1000)
    asm volatile(
        "ld.global.v8.f32 {%0, %1, %2, %3, %4, %5, %6, %7}, [%8];"
        : "=f"(v[0]), "=f"(v[1]), "=f"(v[2]), "=f"(v[3]),
          "=f"(v[4]), "=f"(v[5]), "=f"(v[6]), "=f"(v[7])
        : "l"(p));
#else
    const float4* p4 = (const float4*)p;
    float4 a = p4[0], b = p4[1];
    v[0] = a.x; v[1] = a.y; v[2] = a.z; v[3] = a.w;
    v[4] = b.x; v[5] = b.y; v[6] = b.z; v[7] = b.w;
#endif
}

// ---------------------------------------------------------------------------
// Kernel 1: EdgeConv layer 1.  g_x4 -> scatter-max into g_h1[N,16].
// 2 gather wf + 2 x 256-bit probe wf per edge; probes are stale-safe
// (atomicMax remains the correctness guard).
// ---------------------------------------------------------------------------
__global__ void __launch_bounds__(256) edge1_kernel(
    const int* __restrict__ ei,
    const float* __restrict__ w1a, const float* __restrict__ b1a,
    const float* __restrict__ w1b, const float* __restrict__ b1b) {
    __shared__ float sw1a[96], sb1a[16], sw1b[256], sb1b[16];
    int t = threadIdx.x;
    if (t < 96)  sw1a[t] = w1a[t];
    if (t < 16)  { sb1a[t] = b1a[t]; sb1b[t] = b1b[t]; }
    sw1b[t] = w1b[t];                   // blockDim == 256
    __syncthreads();

    int e = blockIdx.x * 256 + t;
    if (e >= N_EDGES) return;
    int s = ei[e];
    int d = ei[N_EDGES + e];

    float4 xi = __ldg(&g_x4[d]);
    float4 xj = __ldg(&g_x4[s]);
    float in6[6] = {xi.x, xi.y, xi.z, xj.x - xi.x, xj.y - xi.y, xj.z - xi.z};

    float hid[16];
#pragma unroll
    for (int k = 0; k < 16; k++) {
        float a = sb1a[k];
#pragma unroll
        for (int c = 0; c < 6; c++) a = fmaf(in6[c], sw1a[c * 16 + k], a);
        hid[k] = fmaxf(a, 0.f);
    }

    float outv[16];
#pragma unroll
    for (int k = 0; k < 16; k++) {
        float a = sb1b[k];
#pragma unroll
        for (int j = 0; j < 16; j++) a = fmaf(hid[j], sw1b[j * 16 + k], a);
        outv[k] = a;
    }

    // Vector probe of the current accumulator row: 2 x 256-bit loads
    float* dstp = g_h1 + (long long)d * 16;
    float cur[16];
    ld256(dstp, cur);
    ld256(dstp + 8, cur + 8);
#pragma unroll
    for (int k = 0; k < 16; k++) {
        // init 0 => non-positive can't win; stale cur => extra RED, still correct
        if (outv[k] > 0.f && outv[k] > cur[k])
            atomicMax((int*)(dstp + k), __float_as_int(outv[k]));
    }
}

// ---------------------------------------------------------------------------
// Kernel 1.5: per-node factoring of layer 2's first GEMM (coalesced).
// q_i = b2a + h_i@(Wtop - Wbot),  r_i = h_i@Wbot.
// Per-edge then: z4 = relu(q[dst] + r[src]).
// ---------------------------------------------------------------------------
__global__ void __launch_bounds__(256) qr_kernel(
    const float* __restrict__ w2a, const float* __restrict__ b2a) {
    __shared__ float sw[128], sb[4];
    int t = threadIdx.x;
    if (t < 128) sw[t] = w2a[t];
    if (t < 4)   sb[t] = b2a[t];
    __syncthreads();
    int i = blockIdx.x * 256 + t;
    if (i >= N_NODES) return;

    float h[16];
    const float4* hp = (const float4*)(g_h1 + (long long)i * 16);
#pragma unroll
    for (int q = 0; q < 4; q++) {
        float4 c = hp[q];
        h[4 * q] = c.x; h[4 * q + 1] = c.y; h[4 * q + 2] = c.z; h[4 * q + 3] = c.w;
    }

    float q[4], r[4];
#pragma unroll
    for (int n = 0; n < 4; n++) {
        float aq = sb[n], ar = 0.f;
#pragma unroll
        for (int c = 0; c < 16; c++) {
            float wb = sw[(16 + c) * 4 + n];           // Wbot[c][n]
            aq = fmaf(h[c], sw[c * 4 + n] - wb, aq);   // h@(Wtop-Wbot)
            ar = fmaf(h[c], wb, ar);                   // h@Wbot
        }
        q[n] = aq; r[n] = ar;
    }
    g_q[i] = make_float4(q[0], q[1], q[2], q[3]);
    g_r[i] = make_float4(r[0], r[1], r[2], r[3]);
}

// ---------------------------------------------------------------------------
// Kernel 2: EdgeConv layer 2, factored.  Only 3 wavefronts/edge:
// q[d] gather + r[s] gather + out probe. z4=relu(q+r); out=z4@W2b+b2b; max.
// (s==d self-loops are handled naturally: q_i + r_i == b2a + h_i@Wtop.)
// ---------------------------------------------------------------------------
__global__ void __launch_bounds__(256) edge2_kernel(
    const int* __restrict__ ei,
    const float* __restrict__ w2b, const float* __restrict__ b2b,
    float* __restrict__ out) {
    __shared__ float sw[16], sb[4];
    int t = threadIdx.x;
    if (t < 16) sw[t] = w2b[t];
    if (t < 4)  sb[t] = b2b[t];
    __syncthreads();

    int e = blockIdx.x * 256 + t;
    if (e >= N_EDGES) return;
    int s = ei[e];
    int d = ei[N_EDGES + e];

    float4 qv = __ldg(&g_q[d]);
    float4 rv = __ldg(&g_r[s]);
    float z[4] = {fmaxf(qv.x + rv.x, 0.f), fmaxf(qv.y + rv.y, 0.f),
                  fmaxf(qv.z + rv.z, 0.f), fmaxf(qv.w + rv.w, 0.f)};

    float ov[4];
#pragma unroll
    for (int k = 0; k < 4; k++) {
        float a = sb[k];
#pragma unroll
        for (int j = 0; j < 4; j++) a = fmaf(z[j], sw[j * 4 + k], a);
        ov[k] = a;
    }

    float* dstp = out + (long long)d * 4;
    float4 c = *((const float4*)dstp);   // single vector probe; stale-safe
    float cur[4] = {c.x, c.y, c.z, c.w};
#pragma unroll
    for (int k = 0; k < 4; k++) {
        if (!(ov[k] <= cur[k]))
            atomic_max_float(dstp + k, ov[k]);
    }
}

// ---------------------------------------------------------------------------
// Kernel 3: finalize.  -inf -> 0, then log_softmax over the 4 channels.
// ---------------------------------------------------------------------------
__global__ void __launch_bounds__(256) finalize_kernel(float4* __restrict__ out4) {
    int i = blockIdx.x * 256 + threadIdx.x;
    if (i >= N_NODES) return;
    float4 v = out4[i];
    if (!isfinite(v.x)) v.x = 0.f;
    if (!isfinite(v.y)) v.y = 0.f;
    if (!isfinite(v.z)) v.z = 0.f;
    if (!isfinite(v.w)) v.w = 0.f;
    float m = fmaxf(fmaxf(v.x, v.y), fmaxf(v.z, v.w));
    float s = expf(v.x - m) + expf(v.y - m) + expf(v.z - m) + expf(v.w - m);
    float l = m + logf(s);
    v.x -= l; v.y -= l; v.z -= l; v.w -= l;
    out4[i] = v;
}

extern "C" void kernel_launch(void* const* d_in, const int* in_sizes, int n_in,
                              void* d_out, int out_size) {
    const float* x   = (const float*)d_in[0];
    const int*   ei  = (const int*)d_in[1];
    const float* w1a = (const float*)d_in[2];
    const float* b1a = (const float*)d_in[3];
    const float* w1b = (const float*)d_in[4];
    const float* b1b = (const float*)d_in[5];
    const float* w2a = (const float*)d_in[6];
    const float* b2a = (const float*)d_in[7];
    const float* w2b = (const float*)d_in[8];
    const float* b2b = (const float*)d_in[9];
    float* out = (float*)d_out;

    init_kernel<<<2048, 256>>>(x, (float4*)out);
    int eb = (N_EDGES + 255) / 256;
    int nb = (N_NODES + 255) / 256;
    edge1_kernel<<<eb, 256>>>(ei, w1a, b1a, w1b, b1b);
    qr_kernel<<<nb, 256>>>(w2a, b2a);
    edge2_kernel<<<eb, 256>>>(ei, w2b, b2b, out);
    finalize_kernel<<<nb, 256>>>((float4*)out);
}

// round 12
// speedup vs baseline: 1.8773x; 1.0088x over previous
#include <cuda_runtime.h>
#include <math.h>

#define N_NODES 500000
#define N_EDGES 3000000

// Scratch buffers (device globals — no allocation allowed)
__device__ float  g_h1[N_NODES * 16];   // layer-1 fp32 accumulator (atomic target)
__device__ float4 g_x4[N_NODES];        // padded x for single-load gathers
__device__ float4 g_q[N_NODES];         // q_i = b2a + h_i@(Wtop-Wbot)
__device__ float4 g_r[N_NODES];         // r_j = h_j@Wbot

// ---------------------------------------------------------------------------
// Kernel 0: pack x -> float4 table, zero g_h1, set out <- -inf.
// ---------------------------------------------------------------------------
__global__ void init_kernel(const float* __restrict__ x, float4* __restrict__ out4) {
    int i = blockIdx.x * blockDim.x + threadIdx.x;
    int stride = gridDim.x * blockDim.x;
    for (int j = i; j < N_NODES; j += stride)
        g_x4[j] = make_float4(x[3 * j], x[3 * j + 1], x[3 * j + 2], 0.f);
    float4* a = (float4*)g_h1;
    const float4 z = make_float4(0.f, 0.f, 0.f, 0.f);
    for (int j = i; j < N_NODES * 4; j += stride) a[j] = z;
    const float NI = __int_as_float(0xFF800000);  // -inf
    const float4 ni = make_float4(NI, NI, NI, NI);
    for (int j = i; j < N_NODES; j += stride) out4[j] = ni;
}

// float atomic-max via signed/unsigned bit trick (exact, order-independent)
__device__ __forceinline__ void atomic_max_float(float* addr, float v) {
    if (v >= 0.f) atomicMax((int*)addr, __float_as_int(v));
    else          atomicMin((unsigned int*)addr, __float_as_uint(v));
}

// 256-bit load of 8 consecutive floats (Blackwell LDG.E.256).
__device__ __forceinline__ void ld256(const float* p, float* v) {
#if defined(__CUDA_ARCH__) && (__CUDA_ARCH__ >= 1000)
    asm volatile(
        "ld.global.v8.f32 {%0, %1, %2, %3, %4, %5, %6, %7}, [%8];"
        : "=f"(v[0]), "=f"(v[1]), "=f"(v[2]), "=f"(v[3]),
          "=f"(v[4]), "=f"(v[5]), "=f"(v[6]), "=f"(v[7])
        : "l"(p));
#else
    const float4* p4 = (const float4*)p;
    float4 a = p4[0], b = p4[1];
    v[0] = a.x; v[1] = a.y; v[2] = a.z; v[3] = a.w;
    v[4] = b.x; v[5] = b.y; v[6] = b.z; v[7] = b.w;
#endif
}

// ---- packed dual-lane fp32 FMA (sm_100a FFMA2; ptxas won't emit from C++) ----
#if defined(__CUDA_ARCH__) && (__CUDA_ARCH__ >= 1000)
#define HAVE_F32X2 1
__device__ __forceinline__ unsigned long long pk2(float lo, float hi) {
    unsigned long long r;
    asm("mov.b64 %0, {%1, %2};" : "=l"(r) : "f"(lo), "f"(hi));
    return r;
}
__device__ __forceinline__ void upk2(unsigned long long v, float& lo, float& hi) {
    asm("mov.b64 {%0, %1}, %2;" : "=f"(lo), "=f"(hi) : "l"(v));
}
__device__ __forceinline__ void fma2(unsigned long long& d,
                                     unsigned long long a, unsigned long long b) {
    asm("fma.rn.f32x2 %0, %1, %2, %0;" : "+l"(d) : "l"(a), "l"(b));
}
#else
#define HAVE_F32X2 0
#endif

// ---------------------------------------------------------------------------
// Kernel 1: EdgeConv layer 1.  g_x4 -> scatter-max into g_h1[N,16].
// Probe loads hoisted above the GEMMs (latency hides under FMA work);
// GEMMs run on packed f32x2 lanes (half the FMA issues, bit-exact fp32).
// ---------------------------------------------------------------------------
__global__ void __launch_bounds__(256) edge1_kernel(
    const int* __restrict__ ei,
    const float* __restrict__ w1a, const float* __restrict__ b1a,
    const float* __restrict__ w1b, const float* __restrict__ b1b) {
    __shared__ float sw1a[96], sb1a[16], sw1b[256], sb1b[16];
    int t = threadIdx.x;
    if (t < 96)  sw1a[t] = w1a[t];
    if (t < 16)  { sb1a[t] = b1a[t]; sb1b[t] = b1b[t]; }
    sw1b[t] = w1b[t];                   // blockDim == 256
    __syncthreads();

    int e = blockIdx.x * 256 + t;
    if (e >= N_EDGES) return;
    int s = ei[e];
    int d = ei[N_EDGES + e];

    // Hoisted probe: issue the accumulator-row loads NOW; ~250cyc of L2
    // latency overlaps with the gathers + both GEMMs below. Stale-safe.
    float* dstp = g_h1 + (long long)d * 16;
    float cur[16];
    ld256(dstp, cur);
    ld256(dstp + 8, cur + 8);

    float4 xi = __ldg(&g_x4[d]);
    float4 xj = __ldg(&g_x4[s]);
    float in6[6] = {xi.x, xi.y, xi.z, xj.x - xi.x, xj.y - xi.y, xj.z - xi.z};

#if HAVE_F32X2
    // GEMM 1 (6x16) on 8 packed accumulators
    unsigned long long acc[8];
#pragma unroll
    for (int p = 0; p < 8; p++) acc[p] = pk2(sb1a[2 * p], sb1a[2 * p + 1]);
#pragma unroll
    for (int c = 0; c < 6; c++) {
        unsigned long long zc = pk2(in6[c], in6[c]);
        const float* wr = &sw1a[c * 16];
#pragma unroll
        for (int p = 0; p < 8; p++)
            fma2(acc[p], zc, pk2(wr[2 * p], wr[2 * p + 1]));
    }
    float hid[16];
#pragma unroll
    for (int p = 0; p < 8; p++) {
        float lo, hi; upk2(acc[p], lo, hi);
        hid[2 * p] = fmaxf(lo, 0.f); hid[2 * p + 1] = fmaxf(hi, 0.f);
    }
    // GEMM 2 (16x16) on 8 packed accumulators
    unsigned long long acc2[8];
#pragma unroll
    for (int p = 0; p < 8; p++) acc2[p] = pk2(sb1b[2 * p], sb1b[2 * p + 1]);
#pragma unroll
    for (int c = 0; c < 16; c++) {
        unsigned long long zc = pk2(hid[c], hid[c]);
        const float* wr = &sw1b[c * 16];
#pragma unroll
        for (int p = 0; p < 8; p++)
            fma2(acc2[p], zc, pk2(wr[2 * p], wr[2 * p + 1]));
    }
    float outv[16];
#pragma unroll
    for (int p = 0; p < 8; p++) upk2(acc2[p], outv[2 * p], outv[2 * p + 1]);
#else
    float hid[16];
#pragma unroll
    for (int k = 0; k < 16; k++) {
        float a = sb1a[k];
#pragma unroll
        for (int c = 0; c < 6; c++) a = fmaf(in6[c], sw1a[c * 16 + k], a);
        hid[k] = fmaxf(a, 0.f);
    }
    float outv[16];
#pragma unroll
    for (int k = 0; k < 16; k++) {
        float a = sb1b[k];
#pragma unroll
        for (int j = 0; j < 16; j++) a = fmaf(hid[j], sw1b[j * 16 + k], a);
        outv[k] = a;
    }
#endif

#pragma unroll
    for (int k = 0; k < 16; k++) {
        // init 0 => non-positive can't win; stale cur => extra RED, still correct
        if (outv[k] > 0.f && outv[k] > cur[k])
            atomicMax((int*)(dstp + k), __float_as_int(outv[k]));
    }
}

// ---------------------------------------------------------------------------
// Kernel 1.5: per-node factoring of layer 2's first GEMM (coalesced).
// q_i = b2a + h_i@(Wtop - Wbot),  r_i = h_i@Wbot.
// ---------------------------------------------------------------------------
__global__ void __launch_bounds__(256) qr_kernel(
    const float* __restrict__ w2a, const float* __restrict__ b2a) {
    __shared__ float sw[128], sb[4];
    int t = threadIdx.x;
    if (t < 128) sw[t] = w2a[t];
    if (t < 4)   sb[t] = b2a[t];
    __syncthreads();
    int i = blockIdx.x * 256 + t;
    if (i >= N_NODES) return;

    float h[16];
    const float4* hp = (const float4*)(g_h1 + (long long)i * 16);
#pragma unroll
    for (int q = 0; q < 4; q++) {
        float4 c = hp[q];
        h[4 * q] = c.x; h[4 * q + 1] = c.y; h[4 * q + 2] = c.z; h[4 * q + 3] = c.w;
    }

    float q[4], r[4];
#pragma unroll
    for (int n = 0; n < 4; n++) {
        float aq = sb[n], ar = 0.f;
#pragma unroll
        for (int c = 0; c < 16; c++) {
            float wb = sw[(16 + c) * 4 + n];           // Wbot[c][n]
            aq = fmaf(h[c], sw[c * 4 + n] - wb, aq);   // h@(Wtop-Wbot)
            ar = fmaf(h[c], wb, ar);                   // h@Wbot
        }
        q[n] = aq; r[n] = ar;
    }
    g_q[i] = make_float4(q[0], q[1], q[2], q[3]);
    g_r[i] = make_float4(r[0], r[1], r[2], r[3]);
}

// ---------------------------------------------------------------------------
// Kernel 2: EdgeConv layer 2, factored.  3 wavefronts/edge.
// ---------------------------------------------------------------------------
__global__ void __launch_bounds__(256) edge2_kernel(
    const int* __restrict__ ei,
    const float* __restrict__ w2b, const float* __restrict__ b2b,
    float* __restrict__ out) {
    __shared__ float sw[16], sb[4];
    int t = threadIdx.x;
    if (t < 16) sw[t] = w2b[t];
    if (t < 4)  sb[t] = b2b[t];
    __syncthreads();

    int e = blockIdx.x * 256 + t;
    if (e >= N_EDGES) return;
    int s = ei[e];
    int d = ei[N_EDGES + e];

    // Hoist probe load before compute (stale-safe)
    float* dstp = out + (long long)d * 4;
    float4 c = *((const float4*)dstp);

    float4 qv = __ldg(&g_q[d]);
    float4 rv = __ldg(&g_r[s]);
    float z[4] = {fmaxf(qv.x + rv.x, 0.f), fmaxf(qv.y + rv.y, 0.f),
                  fmaxf(qv.z + rv.z, 0.f), fmaxf(qv.w + rv.w, 0.f)};

    float ov[4];
#pragma unroll
    for (int k = 0; k < 4; k++) {
        float a = sb[k];
#pragma unroll
        for (int j = 0; j < 4; j++) a = fmaf(z[j], sw[j * 4 + k], a);
        ov[k] = a;
    }

    float cur[4] = {c.x, c.y, c.z, c.w};
#pragma unroll
    for (int k = 0; k < 4; k++) {
        if (!(ov[k] <= cur[k]))
            atomic_max_float(dstp + k, ov[k]);
    }
}

// ---------------------------------------------------------------------------
// Kernel 3: finalize.  -inf -> 0, then log_softmax over the 4 channels.
// ---------------------------------------------------------------------------
__global__ void __launch_bounds__(256) finalize_kernel(float4* __restrict__ out4) {
    int i = blockIdx.x * 256 + threadIdx.x;
    if (i >= N_NODES) return;
    float4 v = out4[i];
    if (!isfinite(v.x)) v.x = 0.f;
    if (!isfinite(v.y)) v.y = 0.f;
    if (!isfinite(v.z)) v.z = 0.f;
    if (!isfinite(v.w)) v.w = 0.f;
    float m = fmaxf(fmaxf(v.x, v.y), fmaxf(v.z, v.w));
    float s = expf(v.x - m) + expf(v.y - m) + expf(v.z - m) + expf(v.w - m);
    float l = m + logf(s);
    v.x -= l; v.y -= l; v.z -= l; v.w -= l;
    out4[i] = v;
}

extern "C" void kernel_launch(void* const* d_in, const int* in_sizes, int n_in,
                              void* d_out, int out_size) {
    const float* x   = (const float*)d_in[0];
    const int*   ei  = (const int*)d_in[1];
    const float* w1a = (const float*)d_in[2];
    const float* b1a = (const float*)d_in[3];
    const float* w1b = (const float*)d_in[4];
    const float* b1b = (const float*)d_in[5];
    const float* w2a = (const float*)d_in[6];
    const float* b2a = (const float*)d_in[7];
    const float* w2b = (const float*)d_in[8];
    const float* b2b = (const float*)d_in[9];
    float* out = (float*)d_out;

    init_kernel<<<2048, 256>>>(x, (float4*)out);
    int eb = (N_EDGES + 255) / 256;
    int nb = (N_NODES + 255) / 256;
    edge1_kernel<<<eb, 256>>>(ei, w1a, b1a, w1b, b1b);
    qr_kernel<<<nb, 256>>>(w2a, b2a);
    edge2_kernel<<<eb, 256>>>(ei, w2b, b2b, out);
    finalize_kernel<<<nb, 256>>>((float4*)out);
}